// round 14
// baseline (speedup 1.0000x reference)
#include <cuda_runtime.h>
#include <cuda_fp16.h>
#include <cstdint>

#define L_SEQ   2048
#define D_MODEL 1024
#define N_HEADS 16
#define D_HEAD  64
#define N_BATCH 2
#define BH      (N_BATCH * N_HEADS)

// ---------------- device scratch (no allocation) ----------------
__device__ __half g_x[4096 * 1024];          // X single fp16
__device__ __half g_wt[3 * 1024 * 1024];     // [z][n][k] single fp16
__device__ __half g_q[4096 * 1024];          // [BH][L][DH] single fp16
__device__ __half g_k[4096 * 1024];
__device__ __half g_v[4096 * 1024];

// ---------------- helpers ----------------
__device__ __forceinline__ uint32_t smem_u32(const void* p) {
    uint32_t a;
    asm("{ .reg .u64 t; cvta.to.shared.u64 t, %1; cvt.u32.u64 %0, t; }"
        : "=r"(a) : "l"(p));
    return a;
}
__device__ __forceinline__ uint32_t packh2(float e0, float e1) {
    uint32_t r;   // e0 -> low half, e1 -> high half
    asm("cvt.rn.f16x2.f32 %0, %1, %2;" : "=r"(r) : "f"(e1), "f"(e0));
    return r;
}
__device__ __forceinline__ float ex2f(float x) {
    float y; asm("ex2.approx.f32 %0, %1;" : "=f"(y) : "f"(x)); return y;
}
__device__ __forceinline__ void mma16816h(float* c, const uint32_t* a, const uint32_t* b) {
    asm volatile(
        "mma.sync.aligned.m16n8k16.row.col.f32.f16.f16.f32 "
        "{%0,%1,%2,%3}, {%4,%5,%6,%7}, {%8,%9}, {%0,%1,%2,%3};"
        : "+f"(c[0]), "+f"(c[1]), "+f"(c[2]), "+f"(c[3])
        : "r"(a[0]), "r"(a[1]), "r"(a[2]), "r"(a[3]), "r"(b[0]), "r"(b[1]));
}
__device__ __forceinline__ void ldm4(uint32_t* r, uint32_t a) {
    asm volatile("ldmatrix.sync.aligned.m8n8.x4.shared.b16 {%0,%1,%2,%3}, [%4];"
        : "=r"(r[0]), "=r"(r[1]), "=r"(r[2]), "=r"(r[3]) : "r"(a));
}
__device__ __forceinline__ void ldm4t(uint32_t* r, uint32_t a) {
    asm volatile("ldmatrix.sync.aligned.m8n8.x4.trans.shared.b16 {%0,%1,%2,%3}, [%4];"
        : "=r"(r[0]), "=r"(r[1]), "=r"(r[2]), "=r"(r[3]) : "r"(a));
}
__device__ __forceinline__ void cp16(uint32_t dst, const void* src) {
    asm volatile("cp.async.cg.shared.global [%0], [%1], 16;" :: "r"(dst), "l"(src));
}
#define CP_COMMIT() asm volatile("cp.async.commit_group;" ::: "memory")
#define CP_WAIT(n)  asm volatile("cp.async.wait_group %0;" :: "n"(n) : "memory")

// ---------------- Kernel A: X -> single fp16 ----------------
__global__ void conv_x_kernel(const float* __restrict__ X) {
    size_t i = ((size_t)blockIdx.x * 256 + threadIdx.x) * 4;
    float4 v = *(const float4*)(X + i);
    *(uint2*)(g_x + i) = make_uint2(packh2(v.x, v.y), packh2(v.z, v.w));
}

// ---------------- Kernel B: W[k][n] -> Wt[n][k] single fp16 ----------------
__global__ void conv_w_kernel(const float* __restrict__ Wq,
                              const float* __restrict__ Wk,
                              const float* __restrict__ Wv) {
    __shared__ float t[32][33];
    int z = blockIdx.z;
    const float* W = (z == 0) ? Wq : (z == 1) ? Wk : Wv;
    int n0 = blockIdx.x * 32, k0 = blockIdx.y * 32;
    int tx = threadIdx.x, ty = threadIdx.y;
#pragma unroll
    for (int i = 0; i < 4; i++)
        t[ty + 8*i][tx] = W[(size_t)(k0 + ty + 8*i) * D_MODEL + n0 + tx];
    __syncthreads();
    size_t base = (size_t)z * 1024 * 1024;
#pragma unroll
    for (int i = 0; i < 4; i++)
        g_wt[base + (size_t)(n0 + ty + 8*i) * 1024 + k0 + tx] =
            __float2half_rn(t[tx][ty + 8*i]);
}

// ---------------------------------------------------------------------------
// Kernel C: QKV GEMM (1-pass fp16). 128x128 tile, 8 warps 32m x 64n,
// k-chunk 32 double-buffered cp.async. smem 40960 B, 2 CTAs/SM.
// ---------------------------------------------------------------------------
__global__ __launch_bounds__(256, 2) void qkv_mma_kernel(
    const float* __restrict__ bq, const float* __restrict__ bk,
    const float* __restrict__ bv)
{
    extern __shared__ char smem[];
    const uint32_t sb = smem_u32(smem);
    const int z = blockIdx.x >> 8;
    const int rem = blockIdx.x & 255;
    const int n0 = (rem & 7) * 128, m0 = (rem >> 3) * 128;
    const float* bias = (z == 0) ? bq : (z == 1) ? bk : bv;
    __half* outp = (z == 0) ? g_q : (z == 1) ? g_k : g_v;
    const __half* wt = g_wt + (size_t)z * 1024 * 1024;

    const int tid = threadIdx.x, lane = tid & 31, wid = tid >> 5;
    const int gid = lane >> 2, tg = lane & 3;
    const int wm = wid >> 1, wn = wid & 1;
    const int lrow = (lane & 7) + ((lane >> 3) & 1) * 8;
    const int lcolb = (lane >> 4) * 16;

    auto stage = [&](int kc, int buf) {
#pragma unroll
        for (int i = 0; i < 4; i++) {
            int f = i * 256 + tid;
            int tensor = f >> 9, rr = f & 511, r = rr >> 2, c = rr & 3;
            uint32_t dst = sb + buf * 20480 + tensor * 10240 + r * 80 + c * 16;
            const __half* src = tensor
                ? wt  + (size_t)(n0 + r) * 1024 + kc * 32 + c * 8
                : g_x + (size_t)(m0 + r) * 1024 + kc * 32 + c * 8;
            cp16(dst, src);
        }
        CP_COMMIT();
    };

    float acc[2][8][4];
#pragma unroll
    for (int mt = 0; mt < 2; mt++)
#pragma unroll
        for (int nt = 0; nt < 8; nt++)
#pragma unroll
            for (int q = 0; q < 4; q++) acc[mt][nt][q] = 0.0f;

    stage(0, 0);
    for (int kc = 0; kc < 32; kc++) {
        const int buf = kc & 1;
        CP_WAIT(0);
        __syncthreads();
        if (kc < 31) stage(kc + 1, buf ^ 1);

        const uint32_t ab = sb + buf * 20480;
#pragma unroll
        for (int ks = 0; ks < 2; ks++) {
            const int kboff = ks * 32 + lcolb;
            uint32_t af[2][4];
#pragma unroll
            for (int mt = 0; mt < 2; mt++)
                ldm4(af[mt], ab + (wm * 32 + mt * 16 + lrow) * 80 + kboff);
#pragma unroll
            for (int g = 0; g < 4; g++) {
                uint32_t b4[4];
                ldm4(b4, ab + 10240 + (wn * 64 + g * 16 + lrow) * 80 + kboff);
#pragma unroll
                for (int sub = 0; sub < 2; sub++) {
                    uint32_t b2[2] = {b4[sub], b4[sub + 2]};
                    const int nt = g * 2 + sub;
                    mma16816h(acc[0][nt], af[0], b2);
                    mma16816h(acc[1][nt], af[1], b2);
                }
            }
        }
    }

#pragma unroll
    for (int mt = 0; mt < 2; mt++) {
#pragma unroll
        for (int nt = 0; nt < 8; nt++) {
            int n = n0 + wn * 64 + nt * 8 + tg * 2;
            int hh = n >> 6, d = n & 63;
            float b0 = bias[n], b1 = bias[n + 1];
            int mA = m0 + wm * 32 + mt * 16 + gid;
#pragma unroll
            for (int half = 0; half < 2; half++) {
                int m = mA + half * 8;
                int bb = m >> 11, ll = m & 2047;
                size_t dst = (((size_t)(bb * N_HEADS + hh)) * L_SEQ + ll) * D_HEAD + d;
                *(uint32_t*)(outp + dst) =
                    packh2(acc[mt][nt][half * 2] + b0,
                           acc[mt][nt][half * 2 + 1] + b1);
            }
        }
    }
}

// ---------------------------------------------------------------------------
// Kernel D: attention (fp16, 1-pass) with FUSED rel bias: each CTA reads its
// own rel1/rel2 fp32 rows (CTA-exclusive -> zero redundancy), computes
// (r1+r2)*0.125*log2e -> fp16 into the RC smem double-buffer via a register
// path. Chunk A's LDG latency hides under QK, chunk B's under the epilogue.
// R11 structure otherwise: CTA 128 q-rows, j-loop 64, 8 warps, full-CTA
// __syncthreads (publishes both cp.async KV and RC STS of prev iter).
// smem: Q 18432 + K 2x9216 + V 2x9216 + RC 2x18432 + mask 8192 = 100352 B.
// ---------------------------------------------------------------------------
__global__ __launch_bounds__(256, 2) void attn_mma_kernel(
    const float* __restrict__ mask,
    const float* __restrict__ rel1,
    const float* __restrict__ rel2,
    float* __restrict__ out)
{
    extern __shared__ char smem[];
    const uint32_t sb = smem_u32(smem);
    const int KS = 18432, VS = 36864, RC = 55296, MS = 92160;

    const int tid = threadIdx.x, lane = tid & 31, w = tid >> 5;
    const int gid = lane >> 2, tg = lane & 3;
    const int bh = blockIdx.y, b = bh >> 4, h = bh & 15;
    const int i0 = blockIdx.x * 128;
    const int lrow = (lane & 7) + ((lane >> 3) & 1) * 8;
    const int lcolb = (lane >> 4) * 16;
    const float C = 0.1803368801f;           // 0.125 * log2(e)
    const float LOG2E = 1.4426950409f;

    const __half* qp = g_q + (size_t)bh * L_SEQ * D_HEAD;
    const __half* kp = g_k + (size_t)bh * L_SEQ * D_HEAD;
    const __half* vp = g_v + (size_t)bh * L_SEQ * D_HEAD;

    const int r0 = i0 + w * 16 + gid, r1 = r0 + 8;

    // rel staging geometry: thread owns row rr = tid>>1, col half ch = tid&1
    const int relrow = tid >> 1, relch = tid & 1;
    const float* rel1p = rel1 + ((size_t)h * L_SEQ + i0 + relrow) * L_SEQ + relch * 32;
    const float* rel2p = rel2 + ((size_t)h * L_SEQ + i0 + relrow) * L_SEQ + relch * 32;
    const uint32_t rcdst0 = sb + RC + relrow * 144 + relch * 64;

    auto stage_kv = [&](int jt, int buf) {
        const int j0 = jt * 64;
#pragma unroll
        for (int i = 0; i < 4; i++) {
            int f = i * 256 + tid;
            int tensor = f >> 9, rem = f & 511;
            int r = rem >> 3, c = rem & 7;
            uint32_t dst = sb + (tensor ? VS : KS) + buf * 9216 + r * 144 + c * 16;
            const __half* src = tensor ? vp : kp;
            cp16(dst, src + (size_t)(j0 + r) * 64 + c * 8);
        }
        CP_COMMIT();
    };
    // rel chunk load: 4 float4 per stream (16 cols), qb = 0 (A) or 4 (B)
    auto load_rel = [&](int jt, int qb, float4* f1, float4* f2) {
        const float* p1 = rel1p + jt * 64 + qb * 4;
        const float* p2 = rel2p + jt * 64 + qb * 4;
#pragma unroll
        for (int q = 0; q < 4; q++) {
            f1[q] = *(const float4*)(p1 + q * 4);
            f2[q] = *(const float4*)(p2 + q * 4);
        }
    };
    auto sts_rel = [&](int buf, int qb, const float4* f1, const float4* f2) {
        uint32_t wv[8];
#pragma unroll
        for (int q = 0; q < 4; q++) {
            wv[2*q]   = packh2((f1[q].x + f2[q].x) * C, (f1[q].y + f2[q].y) * C);
            wv[2*q+1] = packh2((f1[q].z + f2[q].z) * C, (f1[q].w + f2[q].w) * C);
        }
        uint32_t d = rcdst0 + buf * 18432 + qb * 8;
        asm volatile("st.shared.v4.b32 [%0], {%1,%2,%3,%4};"
            :: "r"(d), "r"(wv[0]), "r"(wv[1]), "r"(wv[2]), "r"(wv[3]) : "memory");
        asm volatile("st.shared.v4.b32 [%0], {%1,%2,%3,%4};"
            :: "r"(d + 16), "r"(wv[4]), "r"(wv[5]), "r"(wv[6]), "r"(wv[7]) : "memory");
    };

    // prologue: Q + KV(0) via cp.async; rel tile 0 -> RC[0]; mask -> smem
#pragma unroll
    for (int i = 0; i < 4; i++) {
        int f = i * 256 + tid;
        int r = f >> 3, c = f & 7;
        cp16(sb + r * 144 + c * 16, qp + (size_t)(i0 + r) * 64 + c * 8);
    }
    stage_kv(0, 0);
    {
        float4 a1[4], a2[4];
        load_rel(0, 0, a1, a2); sts_rel(0, 0, a1, a2);
        load_rel(0, 4, a1, a2); sts_rel(0, 4, a1, a2);
        float* msmem = (float*)(smem + MS);
        const float* mrow = mask + (size_t)b * L_SEQ;
#pragma unroll
        for (int i = 0; i < 8; i++)
            msmem[tid + i * 256] = mrow[tid + i * 256] * LOG2E;
    }

    float o[8][4];
#pragma unroll
    for (int nt = 0; nt < 8; nt++)
#pragma unroll
        for (int q = 0; q < 4; q++) o[nt][q] = 0.0f;
    float lsum0 = 0.0f, lsum1 = 0.0f;

    const float* msmem = (const float*)(smem + MS);
    const int rowA = w * 16 + gid, rowB = rowA + 8;

    for (int jt = 0; jt < 32; jt++) {
        const int j0 = jt * 64;
        const int buf = jt & 1;
        CP_WAIT(0);
        __syncthreads();    // publish KV(jt) cp.async + RC(jt) STS
        if (jt < 31) stage_kv(jt + 1, buf ^ 1);

        // rel(jt+1) chunk A loads — latency hidden under QK
        float4 a1[4], a2[4];
        if (jt < 31) load_rel(jt + 1, 0, a1, a2);

        // ---- S = Q K^T (1-pass) ----
        float s[8][4];
#pragma unroll
        for (int nt = 0; nt < 8; nt++)
#pragma unroll
            for (int q = 0; q < 4; q++) s[nt][q] = 0.0f;
        const uint32_t kb_base = sb + KS + buf * 9216;
#pragma unroll
        for (int ks = 0; ks < 4; ks++) {
            const int kboff = ks * 32 + lcolb;
            uint32_t q4[4];
            ldm4(q4, sb + (w * 16 + lrow) * 144 + kboff);
#pragma unroll
            for (int g = 0; g < 4; g++) {
                uint32_t k4[4];
                ldm4(k4, kb_base + (g * 16 + lrow) * 144 + kboff);
#pragma unroll
                for (int sub = 0; sub < 2; sub++) {
                    uint32_t b2[2] = {k4[sub], k4[sub + 2]};
                    mma16816h(s[g * 2 + sub], q4, b2);
                }
            }
        }

        // store chunk A, launch chunk B (hidden under epilogue)
        float4 b1[4], b2r[4];
        if (jt < 31) {
            sts_rel(buf ^ 1, 0, a1, a2);
            load_rel(jt + 1, 4, b1, b2r);
        }

        // ---- epilogue: p = 2^( s*C + relC + mask*log2e ) -> fp16 ----
        const char* rcb = smem + RC + buf * 18432;
        uint32_t pw[8][2];
#pragma unroll
        for (int nt = 0; nt < 8; nt++) {
            const int jo = nt * 8 + tg * 2;
            float2 rcA = __half22float2(
                *(const __half2*)(rcb + rowA * 144 + jo * 2));
            float2 rcB = __half22float2(
                *(const __half2*)(rcb + rowB * 144 + jo * 2));
            float mk0 = msmem[j0 + jo], mk1 = msmem[j0 + jo + 1];
            float p00 = ex2f(fmaf(s[nt][0], C, rcA.x + mk0));
            float p01 = ex2f(fmaf(s[nt][1], C, rcA.y + mk1));
            float p10 = ex2f(fmaf(s[nt][2], C, rcB.x + mk0));
            float p11 = ex2f(fmaf(s[nt][3], C, rcB.y + mk1));
            lsum0 += p00 + p01;
            lsum1 += p10 + p11;
            pw[nt][0] = packh2(p00, p01);
            pw[nt][1] = packh2(p10, p11);
        }

        // store chunk B (next __syncthreads publishes it)
        if (jt < 31) sts_rel(buf ^ 1, 4, b1, b2r);

        // ---- O += P V (1-pass, V via ldmatrix.trans) ----
        const uint32_t vb_base = sb + VS + buf * 9216;
#pragma unroll
        for (int ks = 0; ks < 4; ks++) {
            uint32_t a4[4] = {pw[2*ks][0], pw[2*ks][1],
                              pw[2*ks+1][0], pw[2*ks+1][1]};
#pragma unroll
            for (int g = 0; g < 4; g++) {
                uint32_t v4[4];
                ldm4t(v4, vb_base + (ks * 16 + lrow) * 144 + g * 32 + lcolb);
#pragma unroll
                for (int sub = 0; sub < 2; sub++) {
                    uint32_t b2v[2] = {v4[sub * 2], v4[sub * 2 + 1]};
                    mma16816h(o[g * 2 + sub], a4, b2v);
                }
            }
        }
    }

    lsum0 += __shfl_xor_sync(0xffffffffu, lsum0, 1);
    lsum0 += __shfl_xor_sync(0xffffffffu, lsum0, 2);
    lsum1 += __shfl_xor_sync(0xffffffffu, lsum1, 1);
    lsum1 += __shfl_xor_sync(0xffffffffu, lsum1, 2);
    float inv0 = 1.0f / lsum0, inv1 = 1.0f / lsum1;

#pragma unroll
    for (int nt = 0; nt < 8; nt++) {
        int d = nt * 8 + tg * 2;
        *(float2*)(out + ((size_t)b * L_SEQ + r0) * D_MODEL + h * 64 + d) =
            make_float2(o[nt][0] * inv0, o[nt][1] * inv0);
        *(float2*)(out + ((size_t)b * L_SEQ + r1) * D_MODEL + h * 64 + d) =
            make_float2(o[nt][2] * inv1, o[nt][3] * inv1);
    }
}

// ---------------- launch ----------------
extern "C" void kernel_launch(void* const* d_in, const int* in_sizes, int n_in,
                              void* d_out, int out_size)
{
    const float* hidden = (const float*)d_in[0];
    const float* mask   = (const float*)d_in[1];
    const float* rel1   = (const float*)d_in[2];
    const float* rel2   = (const float*)d_in[3];
    const float* Wq = (const float*)d_in[4];
    const float* bq = (const float*)d_in[5];
    const float* Wk = (const float*)d_in[6];
    const float* bk = (const float*)d_in[7];
    const float* Wv = (const float*)d_in[8];
    const float* bv = (const float*)d_in[9];
    float* out = (float*)d_out;

    conv_x_kernel<<<4096, 256>>>(hidden);
    conv_w_kernel<<<dim3(32, 32, 3), dim3(32, 8)>>>(Wq, Wk, Wv);

    cudaFuncSetAttribute(qkv_mma_kernel,
                         cudaFuncAttributeMaxDynamicSharedMemorySize, 40960);
    qkv_mma_kernel<<<768, 256, 40960>>>(bq, bk, bv);

    cudaFuncSetAttribute(attn_mma_kernel,
                         cudaFuncAttributeMaxDynamicSharedMemorySize, 100352);
    attn_mma_kernel<<<dim3(16, BH), 256, 100352>>>(mask, rel1, rel2, out);
}

// round 15
// speedup vs baseline: 1.9999x; 1.9999x over previous
#include <cuda_runtime.h>
#include <cuda_fp16.h>
#include <cstdint>

#define L_SEQ   2048
#define D_MODEL 1024
#define N_HEADS 16
#define D_HEAD  64
#define N_BATCH 2
#define BH      (N_BATCH * N_HEADS)

// ---------------- device scratch (no allocation) ----------------
__device__ __half g_x[4096 * 1024];          // X single fp16
__device__ __half g_wt[3 * 1024 * 1024];     // [z][n][k] single fp16
__device__ __half g_q[4096 * 1024];          // [BH][L][DH] single fp16
__device__ __half g_k[4096 * 1024];
__device__ __half g_v[4096 * 1024];
__device__ float  g_mlc[N_BATCH * L_SEQ];    // mask * log2e

// ---------------- helpers ----------------
__device__ __forceinline__ uint32_t smem_u32(const void* p) {
    uint32_t a;
    asm("{ .reg .u64 t; cvta.to.shared.u64 t, %1; cvt.u32.u64 %0, t; }"
        : "=r"(a) : "l"(p));
    return a;
}
__device__ __forceinline__ uint32_t packh2(float e0, float e1) {
    uint32_t r;   // e0 -> low half, e1 -> high half
    asm("cvt.rn.f16x2.f32 %0, %1, %2;" : "=r"(r) : "f"(e1), "f"(e0));
    return r;
}
__device__ __forceinline__ float ex2f(float x) {
    float y; asm("ex2.approx.f32 %0, %1;" : "=f"(y) : "f"(x)); return y;
}
__device__ __forceinline__ void mma16816h(float* c, const uint32_t* a, const uint32_t* b) {
    asm volatile(
        "mma.sync.aligned.m16n8k16.row.col.f32.f16.f16.f32 "
        "{%0,%1,%2,%3}, {%4,%5,%6,%7}, {%8,%9}, {%0,%1,%2,%3};"
        : "+f"(c[0]), "+f"(c[1]), "+f"(c[2]), "+f"(c[3])
        : "r"(a[0]), "r"(a[1]), "r"(a[2]), "r"(a[3]), "r"(b[0]), "r"(b[1]));
}
__device__ __forceinline__ void ldm4(uint32_t* r, uint32_t a) {
    asm volatile("ldmatrix.sync.aligned.m8n8.x4.shared.b16 {%0,%1,%2,%3}, [%4];"
        : "=r"(r[0]), "=r"(r[1]), "=r"(r[2]), "=r"(r[3]) : "r"(a));
}
__device__ __forceinline__ void ldm4t(uint32_t* r, uint32_t a) {
    asm volatile("ldmatrix.sync.aligned.m8n8.x4.trans.shared.b16 {%0,%1,%2,%3}, [%4];"
        : "=r"(r[0]), "=r"(r[1]), "=r"(r[2]), "=r"(r[3]) : "r"(a));
}
__device__ __forceinline__ void cp16(uint32_t dst, const void* src) {
    asm volatile("cp.async.cg.shared.global [%0], [%1], 16;" :: "r"(dst), "l"(src));
}
#define CP_COMMIT() asm volatile("cp.async.commit_group;" ::: "memory")
#define CP_WAIT(n)  asm volatile("cp.async.wait_group %0;" :: "n"(n) : "memory")

// ---------------- Kernel A: X -> single fp16 ----------------
__global__ void conv_x_kernel(const float* __restrict__ X) {
    size_t i = ((size_t)blockIdx.x * 256 + threadIdx.x) * 4;
    float4 v = *(const float4*)(X + i);
    *(uint2*)(g_x + i) = make_uint2(packh2(v.x, v.y), packh2(v.z, v.w));
}

// ---------------- Kernel A2: mask * log2e ----------------
__global__ void mask_kernel(const float* __restrict__ mask) {
    int i = blockIdx.x * 256 + threadIdx.x;
    g_mlc[i] = mask[i] * 1.4426950409f;
}

// ---------------- Kernel B: W[k][n] -> Wt[n][k] single fp16 ----------------
__global__ void conv_w_kernel(const float* __restrict__ Wq,
                              const float* __restrict__ Wk,
                              const float* __restrict__ Wv) {
    __shared__ float t[32][33];
    int z = blockIdx.z;
    const float* W = (z == 0) ? Wq : (z == 1) ? Wk : Wv;
    int n0 = blockIdx.x * 32, k0 = blockIdx.y * 32;
    int tx = threadIdx.x, ty = threadIdx.y;
#pragma unroll
    for (int i = 0; i < 4; i++)
        t[ty + 8*i][tx] = W[(size_t)(k0 + ty + 8*i) * D_MODEL + n0 + tx];
    __syncthreads();
    size_t base = (size_t)z * 1024 * 1024;
#pragma unroll
    for (int i = 0; i < 4; i++)
        g_wt[base + (size_t)(n0 + ty + 8*i) * 1024 + k0 + tx] =
            __float2half_rn(t[tx][ty + 8*i]);
}

// ---------------------------------------------------------------------------
// Kernel C: QKV GEMM (1-pass fp16). 128x128 tile, 8 warps 32m x 64n,
// k-chunk 32 double-buffered cp.async. smem 40960 B, 2 CTAs/SM.
// ---------------------------------------------------------------------------
__global__ __launch_bounds__(256, 2) void qkv_mma_kernel(
    const float* __restrict__ bq, const float* __restrict__ bk,
    const float* __restrict__ bv)
{
    extern __shared__ char smem[];
    const uint32_t sb = smem_u32(smem);
    const int z = blockIdx.x >> 8;
    const int rem = blockIdx.x & 255;
    const int n0 = (rem & 7) * 128, m0 = (rem >> 3) * 128;
    const float* bias = (z == 0) ? bq : (z == 1) ? bk : bv;
    __half* outp = (z == 0) ? g_q : (z == 1) ? g_k : g_v;
    const __half* wt = g_wt + (size_t)z * 1024 * 1024;

    const int tid = threadIdx.x, lane = tid & 31, wid = tid >> 5;
    const int gid = lane >> 2, tg = lane & 3;
    const int wm = wid >> 1, wn = wid & 1;
    const int lrow = (lane & 7) + ((lane >> 3) & 1) * 8;
    const int lcolb = (lane >> 4) * 16;

    auto stage = [&](int kc, int buf) {
#pragma unroll
        for (int i = 0; i < 4; i++) {
            int f = i * 256 + tid;
            int tensor = f >> 9, rr = f & 511, r = rr >> 2, c = rr & 3;
            uint32_t dst = sb + buf * 20480 + tensor * 10240 + r * 80 + c * 16;
            const __half* src = tensor
                ? wt  + (size_t)(n0 + r) * 1024 + kc * 32 + c * 8
                : g_x + (size_t)(m0 + r) * 1024 + kc * 32 + c * 8;
            cp16(dst, src);
        }
        CP_COMMIT();
    };

    float acc[2][8][4];
#pragma unroll
    for (int mt = 0; mt < 2; mt++)
#pragma unroll
        for (int nt = 0; nt < 8; nt++)
#pragma unroll
            for (int q = 0; q < 4; q++) acc[mt][nt][q] = 0.0f;

    stage(0, 0);
    for (int kc = 0; kc < 32; kc++) {
        const int buf = kc & 1;
        CP_WAIT(0);
        __syncthreads();
        if (kc < 31) stage(kc + 1, buf ^ 1);

        const uint32_t ab = sb + buf * 20480;
#pragma unroll
        for (int ks = 0; ks < 2; ks++) {
            const int kboff = ks * 32 + lcolb;
            uint32_t af[2][4];
#pragma unroll
            for (int mt = 0; mt < 2; mt++)
                ldm4(af[mt], ab + (wm * 32 + mt * 16 + lrow) * 80 + kboff);
#pragma unroll
            for (int g = 0; g < 4; g++) {
                uint32_t b4[4];
                ldm4(b4, ab + 10240 + (wn * 64 + g * 16 + lrow) * 80 + kboff);
#pragma unroll
                for (int sub = 0; sub < 2; sub++) {
                    uint32_t b2[2] = {b4[sub], b4[sub + 2]};
                    const int nt = g * 2 + sub;
                    mma16816h(acc[0][nt], af[0], b2);
                    mma16816h(acc[1][nt], af[1], b2);
                }
            }
        }
    }

#pragma unroll
    for (int mt = 0; mt < 2; mt++) {
#pragma unroll
        for (int nt = 0; nt < 8; nt++) {
            int n = n0 + wn * 64 + nt * 8 + tg * 2;
            int hh = n >> 6, d = n & 63;
            float b0 = bias[n], b1 = bias[n + 1];
            int mA = m0 + wm * 32 + mt * 16 + gid;
#pragma unroll
            for (int half = 0; half < 2; half++) {
                int m = mA + half * 8;
                int bb = m >> 11, ll = m & 2047;
                size_t dst = (((size_t)(bb * N_HEADS + hh)) * L_SEQ + ll) * D_HEAD + d;
                *(uint32_t*)(outp + dst) =
                    packh2(acc[mt][nt][half * 2] + b0,
                           acc[mt][nt][half * 2 + 1] + b1);
            }
        }
    }
}

// ---------------------------------------------------------------------------
// Kernel D: attention (fp16, 1-pass) with rel1/rel2 FUSED via cp.async fp32
// smem staging (no register path, no relc pre-pass). j-tile = 32 to fit fp32
// rel double-buffers. Q fragments hoisted out of the j-loop. blockIdx.y maps
// y -> (h = y>>1, b = y&1) so batch-pair CTAs sharing rel rows are 16 ids
// apart (same wave) and the second read hits L2.
// smem: Q 18432 + K 2x4608 + V 2x4608 + rel1 2x18432 + rel2 2x18432
//     = 110592 B -> 2 CTAs/SM.
// ---------------------------------------------------------------------------
__global__ __launch_bounds__(256, 2) void attn_mma_kernel(
    const float* __restrict__ rel1,
    const float* __restrict__ rel2,
    float* __restrict__ out)
{
    extern __shared__ char smem[];
    const uint32_t sb = smem_u32(smem);
    const int QS = 0, KS = 18432, VS = 27648, R1 = 36864, R2 = 73728;

    const int tid = threadIdx.x, lane = tid & 31, w = tid >> 5;
    const int gid = lane >> 2, tg = lane & 3;
    const int h = blockIdx.y >> 1, b = blockIdx.y & 1;
    const int bh = b * N_HEADS + h;
    const int i0 = blockIdx.x * 128;
    const int lrow = (lane & 7) + ((lane >> 3) & 1) * 8;
    const int lcolb = (lane >> 4) * 16;
    const float C = 0.1803368801f;           // 0.125 * log2(e)

    const __half* qp = g_q + (size_t)bh * L_SEQ * D_HEAD;
    const __half* kp = g_k + (size_t)bh * L_SEQ * D_HEAD;
    const __half* vp = g_v + (size_t)bh * L_SEQ * D_HEAD;
    const float* rel1h = rel1 + (size_t)h * L_SEQ * L_SEQ;
    const float* rel2h = rel2 + (size_t)h * L_SEQ * L_SEQ;
    const float* mlp = g_mlc + (size_t)b * L_SEQ;

    const int r0 = i0 + w * 16 + gid, r1r = r0 + 8;

    auto stage_kv = [&](int j0, int buf) {   // K+V: 32 rows x 8 chunks each
#pragma unroll
        for (int i = 0; i < 2; i++) {
            int f = i * 256 + tid;
            int tensor = f >> 8, rem = f & 255;
            int r = rem >> 3, c = rem & 7;
            uint32_t dst = sb + (tensor ? VS : KS) + buf * 4608 + r * 144 + c * 16;
            const __half* src = tensor ? vp : kp;
            cp16(dst, src + (size_t)(j0 + r) * 64 + c * 8);
        }
    };
    auto stage_rc = [&](int j0, int buf) {   // rel fp32: 128 rows x 8 chunks x2
#pragma unroll
        for (int i = 0; i < 8; i++) {
            int f = i * 256 + tid;
            int tensor = f >> 10, rem = f & 1023;
            int r = rem >> 3, c = rem & 7;
            uint32_t dst = sb + (tensor ? R2 : R1) + buf * 18432 + r * 144 + c * 16;
            const float* src = tensor ? rel2h : rel1h;
            cp16(dst, src + (size_t)(i0 + r) * L_SEQ + j0 + c * 4);
        }
    };

    // prologue: Q + KV(0) + rel(0), one commit group
#pragma unroll
    for (int i = 0; i < 4; i++) {
        int f = i * 256 + tid;
        int r = f >> 3, c = f & 7;
        cp16(sb + QS + r * 144 + c * 16, qp + (size_t)(i0 + r) * 64 + c * 8);
    }
    stage_kv(0, 0);
    stage_rc(0, 0);
    CP_COMMIT();

    float o[8][4];
#pragma unroll
    for (int nt = 0; nt < 8; nt++)
#pragma unroll
        for (int q = 0; q < 4; q++) o[nt][q] = 0.0f;
    float lsum0 = 0.0f, lsum1 = 0.0f;
    uint32_t qf[4][4];

    const int rowA = w * 16 + gid, rowB = rowA + 8;

    for (int jt = 0; jt < 64; jt++) {
        const int j0 = jt * 32;
        const int buf = jt & 1;
        CP_WAIT(0);
        __syncthreads();
        if (jt < 63) {
            stage_kv(j0 + 32, buf ^ 1);
            stage_rc(j0 + 32, buf ^ 1);
            CP_COMMIT();
        }
        if (jt == 0) {
#pragma unroll
            for (int ks = 0; ks < 4; ks++)
                ldm4(qf[ks], sb + QS + (w * 16 + lrow) * 144 + ks * 32 + lcolb);
        }

        // ---- S = Q K^T (1-pass, Q frags hoisted) ----
        float s[4][4];
#pragma unroll
        for (int nt = 0; nt < 4; nt++)
#pragma unroll
            for (int q = 0; q < 4; q++) s[nt][q] = 0.0f;
        const uint32_t kb_base = sb + KS + buf * 4608;
#pragma unroll
        for (int ks = 0; ks < 4; ks++) {
            const int kboff = ks * 32 + lcolb;
#pragma unroll
            for (int g = 0; g < 2; g++) {
                uint32_t k4[4];
                ldm4(k4, kb_base + (g * 16 + lrow) * 144 + kboff);
#pragma unroll
                for (int sub = 0; sub < 2; sub++) {
                    uint32_t b2[2] = {k4[sub], k4[sub + 2]};
                    mma16816h(s[g * 2 + sub], qf[ks], b2);
                }
            }
        }

        // ---- epilogue: p = 2^( s*C + (r1+r2)*C + mask*log2e ) -> fp16 ----
        const char* rc1 = smem + R1 + buf * 18432;
        const char* rc2 = smem + R2 + buf * 18432;
        uint32_t pw[4][2];
#pragma unroll
        for (int nt = 0; nt < 4; nt++) {
            const int jo = nt * 8 + tg * 2;
            float2 a1 = *(const float2*)(rc1 + rowA * 144 + jo * 4);
            float2 a2 = *(const float2*)(rc2 + rowA * 144 + jo * 4);
            float2 c1 = *(const float2*)(rc1 + rowB * 144 + jo * 4);
            float2 c2 = *(const float2*)(rc2 + rowB * 144 + jo * 4);
            float2 mk = *(const float2*)(mlp + j0 + jo);
            float p00 = ex2f(fmaf(s[nt][0], C, fmaf(a1.x + a2.x, C, mk.x)));
            float p01 = ex2f(fmaf(s[nt][1], C, fmaf(a1.y + a2.y, C, mk.y)));
            float p10 = ex2f(fmaf(s[nt][2], C, fmaf(c1.x + c2.x, C, mk.x)));
            float p11 = ex2f(fmaf(s[nt][3], C, fmaf(c1.y + c2.y, C, mk.y)));
            lsum0 += p00 + p01;
            lsum1 += p10 + p11;
            pw[nt][0] = packh2(p00, p01);
            pw[nt][1] = packh2(p10, p11);
        }

        // ---- O += P V (1-pass, V via ldmatrix.trans) ----
        const uint32_t vb_base = sb + VS + buf * 4608;
#pragma unroll
        for (int ks2 = 0; ks2 < 2; ks2++) {
            uint32_t a4[4] = {pw[2*ks2][0], pw[2*ks2][1],
                              pw[2*ks2+1][0], pw[2*ks2+1][1]};
#pragma unroll
            for (int g = 0; g < 4; g++) {
                uint32_t v4[4];
                ldm4t(v4, vb_base + (ks2 * 16 + lrow) * 144 + g * 32 + lcolb);
#pragma unroll
                for (int sub = 0; sub < 2; sub++) {
                    uint32_t b2[2] = {v4[sub * 2], v4[sub * 2 + 1]};
                    mma16816h(o[g * 2 + sub], a4, b2);
                }
            }
        }
    }

    lsum0 += __shfl_xor_sync(0xffffffffu, lsum0, 1);
    lsum0 += __shfl_xor_sync(0xffffffffu, lsum0, 2);
    lsum1 += __shfl_xor_sync(0xffffffffu, lsum1, 1);
    lsum1 += __shfl_xor_sync(0xffffffffu, lsum1, 2);
    float inv0 = 1.0f / lsum0, inv1 = 1.0f / lsum1;

#pragma unroll
    for (int nt = 0; nt < 8; nt++) {
        int d = nt * 8 + tg * 2;
        *(float2*)(out + ((size_t)b * L_SEQ + r0) * D_MODEL + h * 64 + d) =
            make_float2(o[nt][0] * inv0, o[nt][1] * inv0);
        *(float2*)(out + ((size_t)b * L_SEQ + r1r) * D_MODEL + h * 64 + d) =
            make_float2(o[nt][2] * inv1, o[nt][3] * inv1);
    }
}

// ---------------- launch ----------------
extern "C" void kernel_launch(void* const* d_in, const int* in_sizes, int n_in,
                              void* d_out, int out_size)
{
    const float* hidden = (const float*)d_in[0];
    const float* mask   = (const float*)d_in[1];
    const float* rel1   = (const float*)d_in[2];
    const float* rel2   = (const float*)d_in[3];
    const float* Wq = (const float*)d_in[4];
    const float* bq = (const float*)d_in[5];
    const float* Wk = (const float*)d_in[6];
    const float* bk = (const float*)d_in[7];
    const float* Wv = (const float*)d_in[8];
    const float* bv = (const float*)d_in[9];
    float* out = (float*)d_out;

    conv_x_kernel<<<4096, 256>>>(hidden);
    mask_kernel<<<16, 256>>>(mask);
    conv_w_kernel<<<dim3(32, 32, 3), dim3(32, 8)>>>(Wq, Wk, Wv);

    cudaFuncSetAttribute(qkv_mma_kernel,
                         cudaFuncAttributeMaxDynamicSharedMemorySize, 40960);
    qkv_mma_kernel<<<768, 256, 40960>>>(bq, bk, bv);

    cudaFuncSetAttribute(attn_mma_kernel,
                         cudaFuncAttributeMaxDynamicSharedMemorySize, 110592);
    attn_mma_kernel<<<dim3(16, BH), 256, 110592>>>(rel1, rel2, out);
}

// round 16
// speedup vs baseline: 2.1140x; 1.0570x over previous
#include <cuda_runtime.h>
#include <cuda_fp16.h>
#include <cstdint>

#define L_SEQ   2048
#define D_MODEL 1024
#define N_HEADS 16
#define D_HEAD  64
#define N_BATCH 2
#define BH      (N_BATCH * N_HEADS)

// ---------------- device scratch (no allocation) ----------------
__device__ __half g_x[4096 * 1024];          // X single fp16
__device__ __half g_wt[3 * 1024 * 1024];     // [z][n][k] single fp16
__device__ __half g_q[4096 * 1024];          // [BH][L][DH] single fp16
__device__ __half g_k[4096 * 1024];
__device__ __half g_v[4096 * 1024];
__device__ float  g_mlc[N_BATCH * L_SEQ];    // mask * log2e

// ---------------- helpers ----------------
__device__ __forceinline__ uint32_t smem_u32(const void* p) {
    uint32_t a;
    asm("{ .reg .u64 t; cvta.to.shared.u64 t, %1; cvt.u32.u64 %0, t; }"
        : "=r"(a) : "l"(p));
    return a;
}
__device__ __forceinline__ uint32_t packh2(float e0, float e1) {
    uint32_t r;   // e0 -> low half, e1 -> high half
    asm("cvt.rn.f16x2.f32 %0, %1, %2;" : "=r"(r) : "f"(e1), "f"(e0));
    return r;
}
__device__ __forceinline__ float ex2f(float x) {
    float y; asm("ex2.approx.f32 %0, %1;" : "=f"(y) : "f"(x)); return y;
}
__device__ __forceinline__ void mma16816h(float* c, const uint32_t* a, const uint32_t* b) {
    asm volatile(
        "mma.sync.aligned.m16n8k16.row.col.f32.f16.f16.f32 "
        "{%0,%1,%2,%3}, {%4,%5,%6,%7}, {%8,%9}, {%0,%1,%2,%3};"
        : "+f"(c[0]), "+f"(c[1]), "+f"(c[2]), "+f"(c[3])
        : "r"(a[0]), "r"(a[1]), "r"(a[2]), "r"(a[3]), "r"(b[0]), "r"(b[1]));
}
__device__ __forceinline__ void ldm4(uint32_t* r, uint32_t a) {
    asm volatile("ldmatrix.sync.aligned.m8n8.x4.shared.b16 {%0,%1,%2,%3}, [%4];"
        : "=r"(r[0]), "=r"(r[1]), "=r"(r[2]), "=r"(r[3]) : "r"(a));
}
__device__ __forceinline__ void ldm4t(uint32_t* r, uint32_t a) {
    asm volatile("ldmatrix.sync.aligned.m8n8.x4.trans.shared.b16 {%0,%1,%2,%3}, [%4];"
        : "=r"(r[0]), "=r"(r[1]), "=r"(r[2]), "=r"(r[3]) : "r"(a));
}
__device__ __forceinline__ void cp16(uint32_t dst, const void* src) {
    asm volatile("cp.async.cg.shared.global [%0], [%1], 16;" :: "r"(dst), "l"(src));
}
#define CP_COMMIT() asm volatile("cp.async.commit_group;" ::: "memory")
#define CP_WAIT(n)  asm volatile("cp.async.wait_group %0;" :: "n"(n) : "memory")

// ---------------- Kernel A: X -> single fp16 ----------------
__global__ void conv_x_kernel(const float* __restrict__ X) {
    size_t i = ((size_t)blockIdx.x * 256 + threadIdx.x) * 4;
    float4 v = *(const float4*)(X + i);
    *(uint2*)(g_x + i) = make_uint2(packh2(v.x, v.y), packh2(v.z, v.w));
}

// ---------------- Kernel A2: mask * log2e ----------------
__global__ void mask_kernel(const float* __restrict__ mask) {
    int i = blockIdx.x * 256 + threadIdx.x;
    g_mlc[i] = mask[i] * 1.4426950409f;
}

// ---------------- Kernel B: W[k][n] -> Wt[n][k] single fp16 ----------------
__global__ void conv_w_kernel(const float* __restrict__ Wq,
                              const float* __restrict__ Wk,
                              const float* __restrict__ Wv) {
    __shared__ float t[32][33];
    int z = blockIdx.z;
    const float* W = (z == 0) ? Wq : (z == 1) ? Wk : Wv;
    int n0 = blockIdx.x * 32, k0 = blockIdx.y * 32;
    int tx = threadIdx.x, ty = threadIdx.y;
#pragma unroll
    for (int i = 0; i < 4; i++)
        t[ty + 8*i][tx] = W[(size_t)(k0 + ty + 8*i) * D_MODEL + n0 + tx];
    __syncthreads();
    size_t base = (size_t)z * 1024 * 1024;
#pragma unroll
    for (int i = 0; i < 4; i++)
        g_wt[base + (size_t)(n0 + ty + 8*i) * 1024 + k0 + tx] =
            __float2half_rn(t[tx][ty + 8*i]);
}

// ---------------------------------------------------------------------------
// Kernel C: QKV GEMM (1-pass fp16). 128x128 tile, 8 warps 32m x 64n,
// k-chunk 32 double-buffered cp.async. smem 40960 B, 2 CTAs/SM.
// ---------------------------------------------------------------------------
__global__ __launch_bounds__(256, 2) void qkv_mma_kernel(
    const float* __restrict__ bq, const float* __restrict__ bk,
    const float* __restrict__ bv)
{
    extern __shared__ char smem[];
    const uint32_t sb = smem_u32(smem);
    const int z = blockIdx.x >> 8;
    const int rem = blockIdx.x & 255;
    const int n0 = (rem & 7) * 128, m0 = (rem >> 3) * 128;
    const float* bias = (z == 0) ? bq : (z == 1) ? bk : bv;
    __half* outp = (z == 0) ? g_q : (z == 1) ? g_k : g_v;
    const __half* wt = g_wt + (size_t)z * 1024 * 1024;

    const int tid = threadIdx.x, lane = tid & 31, wid = tid >> 5;
    const int gid = lane >> 2, tg = lane & 3;
    const int wm = wid >> 1, wn = wid & 1;
    const int lrow = (lane & 7) + ((lane >> 3) & 1) * 8;
    const int lcolb = (lane >> 4) * 16;

    auto stage = [&](int kc, int buf) {
#pragma unroll
        for (int i = 0; i < 4; i++) {
            int f = i * 256 + tid;
            int tensor = f >> 9, rr = f & 511, r = rr >> 2, c = rr & 3;
            uint32_t dst = sb + buf * 20480 + tensor * 10240 + r * 80 + c * 16;
            const __half* src = tensor
                ? wt  + (size_t)(n0 + r) * 1024 + kc * 32 + c * 8
                : g_x + (size_t)(m0 + r) * 1024 + kc * 32 + c * 8;
            cp16(dst, src);
        }
        CP_COMMIT();
    };

    float acc[2][8][4];
#pragma unroll
    for (int mt = 0; mt < 2; mt++)
#pragma unroll
        for (int nt = 0; nt < 8; nt++)
#pragma unroll
            for (int q = 0; q < 4; q++) acc[mt][nt][q] = 0.0f;

    stage(0, 0);
    for (int kc = 0; kc < 32; kc++) {
        const int buf = kc & 1;
        CP_WAIT(0);
        __syncthreads();
        if (kc < 31) stage(kc + 1, buf ^ 1);

        const uint32_t ab = sb + buf * 20480;
#pragma unroll
        for (int ks = 0; ks < 2; ks++) {
            const int kboff = ks * 32 + lcolb;
            uint32_t af[2][4];
#pragma unroll
            for (int mt = 0; mt < 2; mt++)
                ldm4(af[mt], ab + (wm * 32 + mt * 16 + lrow) * 80 + kboff);
#pragma unroll
            for (int g = 0; g < 4; g++) {
                uint32_t b4[4];
                ldm4(b4, ab + 10240 + (wn * 64 + g * 16 + lrow) * 80 + kboff);
#pragma unroll
                for (int sub = 0; sub < 2; sub++) {
                    uint32_t b2[2] = {b4[sub], b4[sub + 2]};
                    const int nt = g * 2 + sub;
                    mma16816h(acc[0][nt], af[0], b2);
                    mma16816h(acc[1][nt], af[1], b2);
                }
            }
        }
    }

#pragma unroll
    for (int mt = 0; mt < 2; mt++) {
#pragma unroll
        for (int nt = 0; nt < 8; nt++) {
            int n = n0 + wn * 64 + nt * 8 + tg * 2;
            int hh = n >> 6, d = n & 63;
            float b0 = bias[n], b1 = bias[n + 1];
            int mA = m0 + wm * 32 + mt * 16 + gid;
#pragma unroll
            for (int half = 0; half < 2; half++) {
                int m = mA + half * 8;
                int bb = m >> 11, ll = m & 2047;
                size_t dst = (((size_t)(bb * N_HEADS + hh)) * L_SEQ + ll) * D_HEAD + d;
                *(uint32_t*)(outp + dst) =
                    packh2(acc[mt][nt][half * 2] + b0,
                           acc[mt][nt][half * 2 + 1] + b1);
            }
        }
    }
}

// ---------------------------------------------------------------------------
// Kernel D: attention, BATCH-MERGED. Grid (16 i-tiles, 16 heads); one CTA
// handles BOTH batch elements so each rel (h,i0,j) block is read exactly
// once chip-wide (536 MB total, structural dedup — no L2 luck needed).
// 512 threads / 16 warps: warp w -> batch w>>3, row group w&7 (16 rows).
// j-tile 32; rel fp32 staged via cp.async double-buffer; combine
// (r1+r2)*C in epilogue. Q frags hoisted.
// smem: Q 2x18432 + K 2x9216 + V 2x9216 + rel1 2x18432 + rel2 2x18432
//     = 147456 B -> 1 CTA/SM (16 warps/SM, DRAM-bound so occupancy ok).
// ---------------------------------------------------------------------------
__global__ __launch_bounds__(512, 1) void attn_mma_kernel(
    const float* __restrict__ rel1,
    const float* __restrict__ rel2,
    float* __restrict__ out)
{
    extern __shared__ char smem[];
    const uint32_t sb = smem_u32(smem);
    const int QS = 0, KS = 36864, VS = 55296, R1 = 73728, R2 = 110592;

    const int tid = threadIdx.x, lane = tid & 31, w = tid >> 5;
    const int gid = lane >> 2, tg = lane & 3;
    const int wb = w >> 3, w8 = w & 7;       // batch, row-group
    const int h = blockIdx.y;
    const int i0 = blockIdx.x * 128;
    const int lrow = (lane & 7) + ((lane >> 3) & 1) * 8;
    const int lcolb = (lane >> 4) * 16;
    const float C = 0.1803368801f;           // 0.125 * log2(e)

    const __half* qp0 = g_q + (size_t)h * L_SEQ * D_HEAD;
    const __half* qp1 = qp0 + (size_t)N_HEADS * L_SEQ * D_HEAD;
    const __half* kp0 = g_k + (size_t)h * L_SEQ * D_HEAD;
    const __half* kp1 = kp0 + (size_t)N_HEADS * L_SEQ * D_HEAD;
    const __half* vp0 = g_v + (size_t)h * L_SEQ * D_HEAD;
    const __half* vp1 = vp0 + (size_t)N_HEADS * L_SEQ * D_HEAD;
    const float* rel1h = rel1 + (size_t)h * L_SEQ * L_SEQ;
    const float* rel2h = rel2 + (size_t)h * L_SEQ * L_SEQ;
    const float* mlp = g_mlc + (size_t)wb * L_SEQ;

    const int r0 = i0 + w8 * 16 + gid, r1r = r0 + 8;

    // stage K+V (both batches, 32 rows) + rel1/rel2 (128 rows fp32): 6/thread
    auto stage_tile = [&](int j0, int buf) {
#pragma unroll
        for (int i = 0; i < 6; i++) {
            int f = i * 512 + tid;
            uint32_t dst; const void* src;
            if (f < 1024) {          // K then V: [tensor][b][r 0-31][c 0-7]
                int tensor = f >> 9, rem = f & 511;
                int bb = rem >> 8, rr = rem & 255, r = rr >> 3, c = rr & 7;
                dst = sb + (tensor ? VS : KS) + buf * 9216 + bb * 4608
                      + r * 144 + c * 16;
                const __half* s = tensor ? (bb ? vp1 : vp0) : (bb ? kp1 : kp0);
                src = s + (size_t)(j0 + r) * 64 + c * 8;
            } else {                 // rel1 then rel2: [tensor][r 0-127][c 0-7]
                int g2 = f - 1024;
                int tensor = g2 >> 10, rem = g2 & 1023;
                int r = rem >> 3, c = rem & 7;
                dst = sb + (tensor ? R2 : R1) + buf * 18432 + r * 144 + c * 16;
                const float* s = tensor ? rel2h : rel1h;
                src = s + (size_t)(i0 + r) * L_SEQ + j0 + c * 4;
            }
            cp16(dst, src);
        }
    };

    // prologue: Q both batches (4/thread) + tile(0), one commit group
#pragma unroll
    for (int i = 0; i < 4; i++) {
        int f = i * 512 + tid;
        int bb = f >> 10, rem = f & 1023, r = rem >> 3, c = rem & 7;
        const __half* s = bb ? qp1 : qp0;
        cp16(sb + QS + bb * 18432 + r * 144 + c * 16,
             s + (size_t)(i0 + r) * 64 + c * 8);
    }
    stage_tile(0, 0);
    CP_COMMIT();

    float o[8][4];
#pragma unroll
    for (int nt = 0; nt < 8; nt++)
#pragma unroll
        for (int q = 0; q < 4; q++) o[nt][q] = 0.0f;
    float lsum0 = 0.0f, lsum1 = 0.0f;
    uint32_t qf[4][4];

    const int rowA = w8 * 16 + gid, rowB = rowA + 8;

    for (int jt = 0; jt < 64; jt++) {
        const int j0 = jt * 32;
        const int buf = jt & 1;
        CP_WAIT(0);
        __syncthreads();
        if (jt < 63) {
            stage_tile(j0 + 32, buf ^ 1);
            CP_COMMIT();
        }
        if (jt == 0) {
#pragma unroll
            for (int ks = 0; ks < 4; ks++)
                ldm4(qf[ks], sb + QS + wb * 18432 + (w8 * 16 + lrow) * 144
                             + ks * 32 + lcolb);
        }

        // ---- S = Q K^T (1-pass, Q frags hoisted) ----
        float s[4][4];
#pragma unroll
        for (int nt = 0; nt < 4; nt++)
#pragma unroll
            for (int q = 0; q < 4; q++) s[nt][q] = 0.0f;
        const uint32_t kb_base = sb + KS + buf * 9216 + wb * 4608;
#pragma unroll
        for (int ks = 0; ks < 4; ks++) {
            const int kboff = ks * 32 + lcolb;
#pragma unroll
            for (int g = 0; g < 2; g++) {
                uint32_t k4[4];
                ldm4(k4, kb_base + (g * 16 + lrow) * 144 + kboff);
#pragma unroll
                for (int sub = 0; sub < 2; sub++) {
                    uint32_t b2[2] = {k4[sub], k4[sub + 2]};
                    mma16816h(s[g * 2 + sub], qf[ks], b2);
                }
            }
        }

        // ---- epilogue: p = 2^( s*C + (r1+r2)*C + mask*log2e ) -> fp16 ----
        const char* rc1 = smem + R1 + buf * 18432;
        const char* rc2 = smem + R2 + buf * 18432;
        uint32_t pw[4][2];
#pragma unroll
        for (int nt = 0; nt < 4; nt++) {
            const int jo = nt * 8 + tg * 2;
            float2 a1 = *(const float2*)(rc1 + rowA * 144 + jo * 4);
            float2 a2 = *(const float2*)(rc2 + rowA * 144 + jo * 4);
            float2 c1 = *(const float2*)(rc1 + rowB * 144 + jo * 4);
            float2 c2 = *(const float2*)(rc2 + rowB * 144 + jo * 4);
            float2 mk = *(const float2*)(mlp + j0 + jo);
            float p00 = ex2f(fmaf(s[nt][0], C, fmaf(a1.x + a2.x, C, mk.x)));
            float p01 = ex2f(fmaf(s[nt][1], C, fmaf(a1.y + a2.y, C, mk.y)));
            float p10 = ex2f(fmaf(s[nt][2], C, fmaf(c1.x + c2.x, C, mk.x)));
            float p11 = ex2f(fmaf(s[nt][3], C, fmaf(c1.y + c2.y, C, mk.y)));
            lsum0 += p00 + p01;
            lsum1 += p10 + p11;
            pw[nt][0] = packh2(p00, p01);
            pw[nt][1] = packh2(p10, p11);
        }

        // ---- O += P V (1-pass, V via ldmatrix.trans) ----
        const uint32_t vb_base = sb + VS + buf * 9216 + wb * 4608;
#pragma unroll
        for (int ks2 = 0; ks2 < 2; ks2++) {
            uint32_t a4[4] = {pw[2*ks2][0], pw[2*ks2][1],
                              pw[2*ks2+1][0], pw[2*ks2+1][1]};
#pragma unroll
            for (int g = 0; g < 4; g++) {
                uint32_t v4[4];
                ldm4t(v4, vb_base + (ks2 * 16 + lrow) * 144 + g * 32 + lcolb);
#pragma unroll
                for (int sub = 0; sub < 2; sub++) {
                    uint32_t b2[2] = {v4[sub * 2], v4[sub * 2 + 1]};
                    mma16816h(o[g * 2 + sub], a4, b2);
                }
            }
        }
    }

    lsum0 += __shfl_xor_sync(0xffffffffu, lsum0, 1);
    lsum0 += __shfl_xor_sync(0xffffffffu, lsum0, 2);
    lsum1 += __shfl_xor_sync(0xffffffffu, lsum1, 1);
    lsum1 += __shfl_xor_sync(0xffffffffu, lsum1, 2);
    float inv0 = 1.0f / lsum0, inv1 = 1.0f / lsum1;

#pragma unroll
    for (int nt = 0; nt < 8; nt++) {
        int d = nt * 8 + tg * 2;
        *(float2*)(out + ((size_t)wb * L_SEQ + r0) * D_MODEL + h * 64 + d) =
            make_float2(o[nt][0] * inv0, o[nt][1] * inv0);
        *(float2*)(out + ((size_t)wb * L_SEQ + r1r) * D_MODEL + h * 64 + d) =
            make_float2(o[nt][2] * inv1, o[nt][3] * inv1);
    }
}

// ---------------- launch ----------------
extern "C" void kernel_launch(void* const* d_in, const int* in_sizes, int n_in,
                              void* d_out, int out_size)
{
    const float* hidden = (const float*)d_in[0];
    const float* mask   = (const float*)d_in[1];
    const float* rel1   = (const float*)d_in[2];
    const float* rel2   = (const float*)d_in[3];
    const float* Wq = (const float*)d_in[4];
    const float* bq = (const float*)d_in[5];
    const float* Wk = (const float*)d_in[6];
    const float* bk = (const float*)d_in[7];
    const float* Wv = (const float*)d_in[8];
    const float* bv = (const float*)d_in[9];
    float* out = (float*)d_out;

    conv_x_kernel<<<4096, 256>>>(hidden);
    mask_kernel<<<16, 256>>>(mask);
    conv_w_kernel<<<dim3(32, 32, 3), dim3(32, 8)>>>(Wq, Wk, Wv);

    cudaFuncSetAttribute(qkv_mma_kernel,
                         cudaFuncAttributeMaxDynamicSharedMemorySize, 40960);
    qkv_mma_kernel<<<768, 256, 40960>>>(bq, bk, bv);

    cudaFuncSetAttribute(attn_mma_kernel,
                         cudaFuncAttributeMaxDynamicSharedMemorySize, 147456);
    attn_mma_kernel<<<dim3(16, N_HEADS), 512, 147456>>>(rel1, rel2, out);
}

// round 17
// speedup vs baseline: 2.1321x; 1.0085x over previous
#include <cuda_runtime.h>
#include <cuda_fp16.h>
#include <cstdint>

#define L_SEQ   2048
#define D_MODEL 1024
#define N_HEADS 16
#define D_HEAD  64
#define N_BATCH 2
#define BH      (N_BATCH * N_HEADS)

#define MERGED_BLOCKS 2816      // = 11 * 256 ; bid%11<3 -> qkv (768), else relc (2048)
#define RELC_BLOCKS   2048

// ---------------- device scratch (no allocation) ----------------
__device__ __half g_x[4096 * 1024];          // X single fp16
__device__ __half g_wt[3 * 1024 * 1024];     // [z][n][k] single fp16
__device__ __half g_q[4096 * 1024];          // [BH][L][DH] single fp16
__device__ __half g_k[4096 * 1024];
__device__ __half g_v[4096 * 1024];
__device__ __half g_relc[16 * 2048 * 2048];  // (rel1+rel2)*0.125*log2e, fp16
__device__ float  g_mlc[N_BATCH * L_SEQ];    // mask * log2e

// ---------------- helpers ----------------
__device__ __forceinline__ uint32_t smem_u32(const void* p) {
    uint32_t a;
    asm("{ .reg .u64 t; cvta.to.shared.u64 t, %1; cvt.u32.u64 %0, t; }"
        : "=r"(a) : "l"(p));
    return a;
}
__device__ __forceinline__ uint32_t packh2(float e0, float e1) {
    uint32_t r;   // e0 -> low half, e1 -> high half
    asm("cvt.rn.f16x2.f32 %0, %1, %2;" : "=r"(r) : "f"(e1), "f"(e0));
    return r;
}
__device__ __forceinline__ float ex2f(float x) {
    float y; asm("ex2.approx.f32 %0, %1;" : "=f"(y) : "f"(x)); return y;
}
__device__ __forceinline__ void mma16816h(float* c, const uint32_t* a, const uint32_t* b) {
    asm volatile(
        "mma.sync.aligned.m16n8k16.row.col.f32.f16.f16.f32 "
        "{%0,%1,%2,%3}, {%4,%5,%6,%7}, {%8,%9}, {%0,%1,%2,%3};"
        : "+f"(c[0]), "+f"(c[1]), "+f"(c[2]), "+f"(c[3])
        : "r"(a[0]), "r"(a[1]), "r"(a[2]), "r"(a[3]), "r"(b[0]), "r"(b[1]));
}
__device__ __forceinline__ void ldm4(uint32_t* r, uint32_t a) {
    asm volatile("ldmatrix.sync.aligned.m8n8.x4.shared.b16 {%0,%1,%2,%3}, [%4];"
        : "=r"(r[0]), "=r"(r[1]), "=r"(r[2]), "=r"(r[3]) : "r"(a));
}
__device__ __forceinline__ void ldm4t(uint32_t* r, uint32_t a) {
    asm volatile("ldmatrix.sync.aligned.m8n8.x4.trans.shared.b16 {%0,%1,%2,%3}, [%4];"
        : "=r"(r[0]), "=r"(r[1]), "=r"(r[2]), "=r"(r[3]) : "r"(a));
}
__device__ __forceinline__ void cp16(uint32_t dst, const void* src) {
    asm volatile("cp.async.cg.shared.global [%0], [%1], 16;" :: "r"(dst), "l"(src));
}
#define CP_COMMIT() asm volatile("cp.async.commit_group;" ::: "memory")
#define CP_WAIT(n)  asm volatile("cp.async.wait_group %0;" :: "n"(n) : "memory")

// ---------------- Kernel A: X -> single fp16 ----------------
__global__ void conv_x_kernel(const float* __restrict__ X) {
    size_t i = ((size_t)blockIdx.x * 256 + threadIdx.x) * 4;
    float4 v = *(const float4*)(X + i);
    *(uint2*)(g_x + i) = make_uint2(packh2(v.x, v.y), packh2(v.z, v.w));
}

// ---------------- Kernel A2: mask * log2e ----------------
__global__ void mask_kernel(const float* __restrict__ mask) {
    int i = blockIdx.x * 256 + threadIdx.x;
    g_mlc[i] = mask[i] * 1.4426950409f;
}

// ---------------- Kernel B: W[k][n] -> Wt[n][k] single fp16 ----------------
__global__ void conv_w_kernel(const float* __restrict__ Wq,
                              const float* __restrict__ Wk,
                              const float* __restrict__ Wv) {
    __shared__ float t[32][33];
    int z = blockIdx.z;
    const float* W = (z == 0) ? Wq : (z == 1) ? Wk : Wv;
    int n0 = blockIdx.x * 32, k0 = blockIdx.y * 32;
    int tx = threadIdx.x, ty = threadIdx.y;
#pragma unroll
    for (int i = 0; i < 4; i++)
        t[ty + 8*i][tx] = W[(size_t)(k0 + ty + 8*i) * D_MODEL + n0 + tx];
    __syncthreads();
    size_t base = (size_t)z * 1024 * 1024;
#pragma unroll
    for (int i = 0; i < 4; i++)
        g_wt[base + (size_t)(n0 + ty + 8*i) * 1024 + k0 + tx] =
            __float2half_rn(t[tx][ty + 8*i]);
}

// ---------------------------------------------------------------------------
// Kernel C (merged, interleaved): bid%11<3 -> QKV GEMM tile; else relc stream.
// Interleaving puts tensor-bound and DRAM-bound CTAs in the same wave.
// ---------------------------------------------------------------------------
__global__ __launch_bounds__(256, 2) void qkv_relc_kernel(
    const float* __restrict__ bq, const float* __restrict__ bk,
    const float* __restrict__ bv,
    const float* __restrict__ rel1, const float* __restrict__ rel2)
{
    const int grp = blockIdx.x / 11, sl = blockIdx.x % 11;
    if (sl >= 3) {
        const float C = 0.1803368801f;   // 0.125 * log2(e)
        const int rbid = grp * 8 + (sl - 3);
        size_t base = ((size_t)rbid * 256 + threadIdx.x) * 4;
        const size_t stride = (size_t)RELC_BLOCKS * 256 * 4;
#pragma unroll 4
        for (int it = 0; it < 32; it++) {
            size_t i = base + (size_t)it * stride;
            float4 a = *(const float4*)(rel1 + i);
            float4 b = *(const float4*)(rel2 + i);
            *(uint2*)(g_relc + i) = make_uint2(
                packh2((a.x + b.x) * C, (a.y + b.y) * C),
                packh2((a.z + b.z) * C, (a.w + b.w) * C));
        }
        return;
    }

    extern __shared__ char smem[];
    const uint32_t sb = smem_u32(smem);
    const int qid = grp * 3 + sl;
    const int z = qid >> 8;
    const int rem = qid & 255;
    const int n0 = (rem & 7) * 128, m0 = (rem >> 3) * 128;
    const float* bias = (z == 0) ? bq : (z == 1) ? bk : bv;
    __half* outp = (z == 0) ? g_q : (z == 1) ? g_k : g_v;
    const __half* wt = g_wt + (size_t)z * 1024 * 1024;

    const int tid = threadIdx.x, lane = tid & 31, wid = tid >> 5;
    const int gid = lane >> 2, tg = lane & 3;
    const int wm = wid >> 1, wn = wid & 1;
    const int lrow = (lane & 7) + ((lane >> 3) & 1) * 8;
    const int lcolb = (lane >> 4) * 16;

    auto stage = [&](int kc, int buf) {
#pragma unroll
        for (int i = 0; i < 4; i++) {
            int f = i * 256 + tid;
            int tensor = f >> 9, rr = f & 511, r = rr >> 2, c = rr & 3;
            uint32_t dst = sb + buf * 20480 + tensor * 10240 + r * 80 + c * 16;
            const __half* src = tensor
                ? wt  + (size_t)(n0 + r) * 1024 + kc * 32 + c * 8
                : g_x + (size_t)(m0 + r) * 1024 + kc * 32 + c * 8;
            cp16(dst, src);
        }
        CP_COMMIT();
    };

    float acc[2][8][4];
#pragma unroll
    for (int mt = 0; mt < 2; mt++)
#pragma unroll
        for (int nt = 0; nt < 8; nt++)
#pragma unroll
            for (int q = 0; q < 4; q++) acc[mt][nt][q] = 0.0f;

    stage(0, 0);
    for (int kc = 0; kc < 32; kc++) {
        const int buf = kc & 1;
        CP_WAIT(0);
        __syncthreads();
        if (kc < 31) stage(kc + 1, buf ^ 1);

        const uint32_t ab = sb + buf * 20480;
#pragma unroll
        for (int ks = 0; ks < 2; ks++) {
            const int kboff = ks * 32 + lcolb;
            uint32_t af[2][4];
#pragma unroll
            for (int mt = 0; mt < 2; mt++)
                ldm4(af[mt], ab + (wm * 32 + mt * 16 + lrow) * 80 + kboff);
#pragma unroll
            for (int g = 0; g < 4; g++) {
                uint32_t b4[4];
                ldm4(b4, ab + 10240 + (wn * 64 + g * 16 + lrow) * 80 + kboff);
#pragma unroll
                for (int sub = 0; sub < 2; sub++) {
                    uint32_t b2[2] = {b4[sub], b4[sub + 2]};
                    const int nt = g * 2 + sub;
                    mma16816h(acc[0][nt], af[0], b2);
                    mma16816h(acc[1][nt], af[1], b2);
                }
            }
        }
    }

#pragma unroll
    for (int mt = 0; mt < 2; mt++) {
#pragma unroll
        for (int nt = 0; nt < 8; nt++) {
            int n = n0 + wn * 64 + nt * 8 + tg * 2;
            int hh = n >> 6, d = n & 63;
            float b0 = bias[n], b1 = bias[n + 1];
            int mA = m0 + wm * 32 + mt * 16 + gid;
#pragma unroll
            for (int half = 0; half < 2; half++) {
                int m = mA + half * 8;
                int bb = m >> 11, ll = m & 2047;
                size_t dst = (((size_t)(bb * N_HEADS + hh)) * L_SEQ + ll) * D_HEAD + d;
                *(uint32_t*)(outp + dst) =
                    packh2(acc[mt][nt][half * 2] + b0,
                           acc[mt][nt][half * 2 + 1] + b1);
            }
        }
    }
}

// ---------------------------------------------------------------------------
// Kernel D: attention, BATCH-MERGED grid + fp16 relC. Grid (16 i-tiles,
// 16 heads); one CTA handles BOTH batch elements -> each relC (h,i0,j) block
// is read exactly once chip-wide (268 MB total). 512 threads / 16 warps:
// warp w -> batch w>>3, row-group w&7 (16 rows of the 128-row i-tile).
// j-tile 64; relC fp16 (premultiplied by 0.125*log2e) + K/V double-buffered
// via cp.async; mask*log2e from L2-resident g_mlc; exp via ex2; P in regs.
// smem: Q 2b x 18432 + K 2buf x (2b x 9216) + V same + RC 2buf x 18432
//     = 147456 B -> 1 CTA/SM (16 warps/SM).
// ---------------------------------------------------------------------------
__global__ __launch_bounds__(512, 1) void attn_mma_kernel(float* __restrict__ out)
{
    extern __shared__ char smem[];
    const uint32_t sb = smem_u32(smem);
    const int QS = 0, KS = 36864, VS = 73728, RC = 110592;

    const int tid = threadIdx.x, lane = tid & 31, w = tid >> 5;
    const int gid = lane >> 2, tg = lane & 3;
    const int wb = w >> 3, w8 = w & 7;       // batch, row-group
    const int h = blockIdx.y;
    const int i0 = blockIdx.x * 128;
    const int lrow = (lane & 7) + ((lane >> 3) & 1) * 8;
    const int lcolb = (lane >> 4) * 16;
    const float C = 0.1803368801f;           // 0.125 * log2(e)

    const __half* qp0 = g_q + (size_t)h * L_SEQ * D_HEAD;
    const __half* qp1 = qp0 + (size_t)N_HEADS * L_SEQ * D_HEAD;
    const __half* kp0 = g_k + (size_t)h * L_SEQ * D_HEAD;
    const __half* kp1 = kp0 + (size_t)N_HEADS * L_SEQ * D_HEAD;
    const __half* vp0 = g_v + (size_t)h * L_SEQ * D_HEAD;
    const __half* vp1 = vp0 + (size_t)N_HEADS * L_SEQ * D_HEAD;
    const __half* rcg = g_relc + (size_t)h * L_SEQ * L_SEQ;
    const float* mlp = g_mlc + (size_t)wb * L_SEQ;

    const int r0 = i0 + w8 * 16 + gid, r1r = r0 + 8;

    // per-iter staging: K 2b x 64r, V 2b x 64r (fp16), RC 128r x 64j fp16
    // = 1024 + 1024 + 1024 cp16 = 6 per thread
    auto stage_tile = [&](int j0, int buf) {
#pragma unroll
        for (int i = 0; i < 6; i++) {
            int f = i * 512 + tid;
            uint32_t dst; const __half* src;
            if (f < 2048) {          // K then V: [tensor][b][r 0-63][c 0-7]
                int tensor = f >> 10, rem = f & 1023;
                int bb = rem >> 9, rr = rem & 511, r = rr >> 3, c = rr & 7;
                dst = sb + (tensor ? VS : KS) + buf * 18432 + bb * 9216
                      + r * 144 + c * 16;
                const __half* s = tensor ? (bb ? vp1 : vp0) : (bb ? kp1 : kp0);
                src = s + (size_t)(j0 + r) * 64 + c * 8;
            } else {                 // relC: [r 0-127][c 0-7]
                int g2 = f - 2048;
                int r = g2 >> 3, c = g2 & 7;
                dst = sb + RC + buf * 18432 + r * 144 + c * 16;
                src = rcg + (size_t)(i0 + r) * L_SEQ + j0 + c * 8;
            }
            cp16(dst, src);
        }
    };

    // prologue: Q both batches (4/thread) + tile(0), one commit group
#pragma unroll
    for (int i = 0; i < 4; i++) {
        int f = i * 512 + tid;
        int bb = f >> 10, rem = f & 1023, r = rem >> 3, c = rem & 7;
        const __half* s = bb ? qp1 : qp0;
        cp16(sb + QS + bb * 18432 + r * 144 + c * 16,
             s + (size_t)(i0 + r) * 64 + c * 8);
    }
    stage_tile(0, 0);
    CP_COMMIT();

    float o[8][4];
#pragma unroll
    for (int nt = 0; nt < 8; nt++)
#pragma unroll
        for (int q = 0; q < 4; q++) o[nt][q] = 0.0f;
    float lsum0 = 0.0f, lsum1 = 0.0f;
    uint32_t qf[4][4];

    const int rowA = w8 * 16 + gid, rowB = rowA + 8;

    for (int jt = 0; jt < 32; jt++) {
        const int j0 = jt * 64;
        const int buf = jt & 1;
        CP_WAIT(0);
        __syncthreads();
        if (jt < 31) {
            stage_tile(j0 + 64, buf ^ 1);
            CP_COMMIT();
        }
        if (jt == 0) {
#pragma unroll
            for (int ks = 0; ks < 4; ks++)
                ldm4(qf[ks], sb + QS + wb * 18432 + (w8 * 16 + lrow) * 144
                             + ks * 32 + lcolb);
        }

        // ---- S = Q K^T (1-pass, Q frags hoisted), 64 j-cols ----
        float s[8][4];
#pragma unroll
        for (int nt = 0; nt < 8; nt++)
#pragma unroll
            for (int q = 0; q < 4; q++) s[nt][q] = 0.0f;
        const uint32_t kb_base = sb + KS + buf * 18432 + wb * 9216;
#pragma unroll
        for (int ks = 0; ks < 4; ks++) {
            const int kboff = ks * 32 + lcolb;
#pragma unroll
            for (int g = 0; g < 4; g++) {
                uint32_t k4[4];
                ldm4(k4, kb_base + (g * 16 + lrow) * 144 + kboff);
#pragma unroll
                for (int sub = 0; sub < 2; sub++) {
                    uint32_t b2[2] = {k4[sub], k4[sub + 2]};
                    mma16816h(s[g * 2 + sub], qf[ks], b2);
                }
            }
        }

        // ---- epilogue: p = 2^( s*C + relC + mask*log2e ) -> fp16 ----
        const char* rcb = smem + RC + buf * 18432;
        uint32_t pw[8][2];
#pragma unroll
        for (int nt = 0; nt < 8; nt++) {
            const int jo = nt * 8 + tg * 2;
            float2 rcA = __half22float2(
                *(const __half2*)(rcb + rowA * 144 + jo * 2));
            float2 rcB = __half22float2(
                *(const __half2*)(rcb + rowB * 144 + jo * 2));
            float2 mk = *(const float2*)(mlp + j0 + jo);
            float p00 = ex2f(fmaf(s[nt][0], C, rcA.x + mk.x));
            float p01 = ex2f(fmaf(s[nt][1], C, rcA.y + mk.y));
            float p10 = ex2f(fmaf(s[nt][2], C, rcB.x + mk.x));
            float p11 = ex2f(fmaf(s[nt][3], C, rcB.y + mk.y));
            lsum0 += p00 + p01;
            lsum1 += p10 + p11;
            pw[nt][0] = packh2(p00, p01);
            pw[nt][1] = packh2(p10, p11);
        }

        // ---- O += P V (1-pass, V via ldmatrix.trans) ----
        const uint32_t vb_base = sb + VS + buf * 18432 + wb * 9216;
#pragma unroll
        for (int ks = 0; ks < 4; ks++) {
            uint32_t a4[4] = {pw[2*ks][0], pw[2*ks][1],
                              pw[2*ks+1][0], pw[2*ks+1][1]};
#pragma unroll
            for (int g = 0; g < 4; g++) {
                uint32_t v4[4];
                ldm4t(v4, vb_base + (ks * 16 + lrow) * 144 + g * 32 + lcolb);
#pragma unroll
                for (int sub = 0; sub < 2; sub++) {
                    uint32_t b2[2] = {v4[sub * 2], v4[sub * 2 + 1]};
                    mma16816h(o[g * 2 + sub], a4, b2);
                }
            }
        }
    }

    lsum0 += __shfl_xor_sync(0xffffffffu, lsum0, 1);
    lsum0 += __shfl_xor_sync(0xffffffffu, lsum0, 2);
    lsum1 += __shfl_xor_sync(0xffffffffu, lsum1, 1);
    lsum1 += __shfl_xor_sync(0xffffffffu, lsum1, 2);
    float inv0 = 1.0f / lsum0, inv1 = 1.0f / lsum1;

#pragma unroll
    for (int nt = 0; nt < 8; nt++) {
        int d = nt * 8 + tg * 2;
        *(float2*)(out + ((size_t)wb * L_SEQ + r0) * D_MODEL + h * 64 + d) =
            make_float2(o[nt][0] * inv0, o[nt][1] * inv0);
        *(float2*)(out + ((size_t)wb * L_SEQ + r1r) * D_MODEL + h * 64 + d) =
            make_float2(o[nt][2] * inv1, o[nt][3] * inv1);
    }
}

// ---------------- launch ----------------
extern "C" void kernel_launch(void* const* d_in, const int* in_sizes, int n_in,
                              void* d_out, int out_size)
{
    const float* hidden = (const float*)d_in[0];
    const float* mask   = (const float*)d_in[1];
    const float* rel1   = (const float*)d_in[2];
    const float* rel2   = (const float*)d_in[3];
    const float* Wq = (const float*)d_in[4];
    const float* bq = (const float*)d_in[5];
    const float* Wk = (const float*)d_in[6];
    const float* bk = (const float*)d_in[7];
    const float* Wv = (const float*)d_in[8];
    const float* bv = (const float*)d_in[9];
    float* out = (float*)d_out;

    conv_x_kernel<<<4096, 256>>>(hidden);
    mask_kernel<<<16, 256>>>(mask);
    conv_w_kernel<<<dim3(32, 32, 3), dim3(32, 8)>>>(Wq, Wk, Wv);

    cudaFuncSetAttribute(qkv_relc_kernel,
                         cudaFuncAttributeMaxDynamicSharedMemorySize, 40960);
    qkv_relc_kernel<<<MERGED_BLOCKS, 256, 40960>>>(bq, bk, bv, rel1, rel2);

    cudaFuncSetAttribute(attn_mma_kernel,
                         cudaFuncAttributeMaxDynamicSharedMemorySize, 147456);
    attn_mma_kernel<<<dim3(16, N_HEADS), 512, 147456>>>(out);
}